// round 1
// baseline (speedup 1.0000x reference)
#include <cuda_runtime.h>

// Problem constants (fixed by the reference setup)
#define NB      512
#define NELEC   100
#define NATOMS  20
#define SHPA    30
#define NORB    300
#define NCTR    2
#define NBAS    600

#define ECHUNK  25                      // electrons per CTA
#define NCHUNK  (NELEC / ECHUNK)        // 4
#define NTHREADS 320                    // 300 active (one per orbital)

__global__ void __launch_bounds__(NTHREADS)
ao_kernel(const float* __restrict__ pos,
          const float* __restrict__ atom_coords,
          const float* __restrict__ bas_exp,
          const float* __restrict__ bas_n,
          const float* __restrict__ norm_cst,
          const float* __restrict__ bas_coeffs,
          const int*   __restrict__ bas_kxyz,
          float* __restrict__ out)
{
    __shared__ float s_pos[ECHUNK * 3];

    const int b   = blockIdx.x;
    const int e0  = blockIdx.y * ECHUNK;
    const int tid = threadIdx.x;

    // Stage this chunk's electron positions into shared memory.
    if (tid < ECHUNK * 3)
        s_pos[tid] = pos[(size_t)b * (NELEC * 3) + e0 * 3 + tid];
    __syncthreads();

    if (tid >= NORB) return;
    const int o  = tid;
    const int ba = 2 * o;        // first basis of this orbital
    const int bb = 2 * o + 1;    // second basis (same atom: SHPA is even)

    // ---- loop-invariant per-basis constants (registers) ----
    const int atom = ba / SHPA;
    const float cx = atom_coords[atom * 3 + 0];
    const float cy = atom_coords[atom * 3 + 1];
    const float cz = atom_coords[atom * 3 + 2];

    const float na0 = -bas_exp[ba];
    const float na1 = -bas_exp[bb];
    const float c0  = norm_cst[ba] * bas_coeffs[ba];
    const float c1  = norm_cst[bb] * bas_coeffs[bb];

    const int n0 = (int)bas_n[ba];
    const int n1 = (int)bas_n[bb];
    const int kx0 = bas_kxyz[ba * 3 + 0], ky0 = bas_kxyz[ba * 3 + 1], kz0 = bas_kxyz[ba * 3 + 2];
    const int kx1 = bas_kxyz[bb * 3 + 0], ky1 = bas_kxyz[bb * 3 + 1], kz1 = bas_kxyz[bb * 3 + 2];

    // Precompute predicates so the inner loop is pure FSEL.
    const bool n0_1 = (n0 == 1),  n0_2 = (n0 == 2);
    const bool n1_1 = (n1 == 1),  n1_2 = (n1 == 2);
    const bool kx0_1 = (kx0 == 1), kx0_2 = (kx0 == 2);
    const bool ky0_1 = (ky0 == 1), ky0_2 = (ky0 == 2);
    const bool kz0_1 = (kz0 == 1), kz0_2 = (kz0 == 2);
    const bool kx1_1 = (kx1 == 1), kx1_2 = (kx1 == 2);
    const bool ky1_1 = (ky1 == 1), ky1_2 = (ky1 == 2);
    const bool kz1_1 = (kz1 == 1), kz1_2 = (kz1 == 2);

    float* op = out + ((size_t)b * NELEC + e0) * NORB + o;

    #pragma unroll 1
    for (int e = 0; e < ECHUNK; ++e) {
        const float ex = s_pos[e * 3 + 0];
        const float ey = s_pos[e * 3 + 1];
        const float ez = s_pos[e * 3 + 2];

        const float dx = ex - cx, dy = ey - cy, dz = ez - cz;
        const float dx2 = dx * dx, dy2 = dy * dy, dz2 = dz * dz;
        const float r2 = dx2 + dy2 + dz2;
        const float r  = sqrtf(r2);

        const float g0 = __expf(na0 * r2);
        const float g1 = __expf(na1 * r2);

        const float rn0 = n0_1 ? r : (n0_2 ? r2 : 1.0f);
        const float rn1 = n1_1 ? r : (n1_2 ? r2 : 1.0f);

        const float X0 = kx0_1 ? dx : (kx0_2 ? dx2 : 1.0f);
        const float Y0 = ky0_1 ? dy : (ky0_2 ? dy2 : 1.0f);
        const float Z0 = kz0_1 ? dz : (kz0_2 ? dz2 : 1.0f);
        const float X1 = kx1_1 ? dx : (kx1_2 ? dx2 : 1.0f);
        const float Y1 = ky1_1 ? dy : (ky1_2 ? dy2 : 1.0f);
        const float Z1 = kz1_1 ? dz : (kz1_2 ? dz2 : 1.0f);

        const float v0 = (c0 * g0) * rn0 * (X0 * (Y0 * Z0));
        const float v1 = (c1 * g1) * rn1 * (X1 * (Y1 * Z1));

        *op = v0 + v1;
        op += NORB;
    }
}

extern "C" void kernel_launch(void* const* d_in, const int* in_sizes, int n_in,
                              void* d_out, int out_size)
{
    const float* pos         = (const float*)d_in[0];
    const float* atom_coords = (const float*)d_in[1];
    const float* bas_exp     = (const float*)d_in[2];
    const float* bas_n       = (const float*)d_in[3];
    const float* norm_cst    = (const float*)d_in[4];
    const float* bas_coeffs  = (const float*)d_in[5];
    const int*   bas_kxyz    = (const int*)d_in[6];
    // d_in[7] = index_ctr: repeat(arange(NORB), NCTR) — encoded structurally above.
    float* out = (float*)d_out;

    dim3 grid(NB, NCHUNK);
    ao_kernel<<<grid, NTHREADS>>>(pos, atom_coords, bas_exp, bas_n,
                                  norm_cst, bas_coeffs, bas_kxyz, out);
}

// round 4
// speedup vs baseline: 2.3761x; 2.3761x over previous
#include <cuda_runtime.h>

#define NB      512
#define NELEC   100
#define SHPA    30
#define NORB    300

#define ECHUNK  20               // electrons per CTA (even: processed in f32x2 pairs)
#define NCHUNK  5                // 100 / 20
#define NPAIRS  (ECHUNK / 2)
#define NTHREADS 320             // 300 active (one per orbital)

typedef unsigned long long u64;

// ---- f32x2 packed helpers (ptxas never auto-fuses; PTX-only path) ----
__device__ __forceinline__ u64 pk2(float lo, float hi) {
    u64 r; asm("mov.b64 %0,{%1,%2};" : "=l"(r) : "f"(lo), "f"(hi)); return r;
}
__device__ __forceinline__ void upk2(u64 v, float& lo, float& hi) {
    asm("mov.b64 {%0,%1}, %2;" : "=f"(lo), "=f"(hi) : "l"(v));
}
__device__ __forceinline__ u64 fma2(u64 a, u64 b, u64 c) {
    u64 d; asm("fma.rn.f32x2 %0,%1,%2,%3;" : "=l"(d) : "l"(a), "l"(b), "l"(c)); return d;
}
__device__ __forceinline__ u64 mul2(u64 a, u64 b) {
    u64 d; asm("mul.rn.f32x2 %0,%1,%2;" : "=l"(d) : "l"(a), "l"(b)); return d;
}
__device__ __forceinline__ u64 add2(u64 a, u64 b) {
    u64 d; asm("add.rn.f32x2 %0,%1,%2;" : "=l"(d) : "l"(a), "l"(b)); return d;
}
__device__ __forceinline__ float ex2f(float x) {
    float y; asm("ex2.approx.ftz.f32 %0, %1;" : "=f"(y) : "f"(x)); return y;
}
__device__ __forceinline__ float rsqf(float x) {
    float y; asm("rsqrt.approx.ftz.f32 %0, %1;" : "=f"(y) : "f"(x)); return y;
}

#define LOG2E 1.4426950408889634f

__global__ void __launch_bounds__(NTHREADS, 2)
ao_kernel(const float* __restrict__ pos,
          const float* __restrict__ atom_coords,
          const float* __restrict__ bas_exp,
          const float* __restrict__ bas_n,
          const float* __restrict__ norm_cst,
          const float* __restrict__ bas_coeffs,
          const int*   __restrict__ bas_kxyz,
          float* __restrict__ out)
{
    __shared__ __align__(16) float s_pos[3][ECHUNK];   // transposed: [comp][electron]

    const int b   = blockIdx.x;
    const int e0  = blockIdx.y * ECHUNK;
    const int tid = threadIdx.x;

    // Stage this chunk's electron positions, transposed for LDS.64 pair loads.
    if (tid < ECHUNK * 3) {
        const int e = tid / 3, c = tid % 3;
        s_pos[c][e] = pos[(size_t)b * (NELEC * 3) + (e0 + e) * 3 + c];
    }
    __syncthreads();

    if (tid >= NORB) return;
    const int o  = tid;
    const int ba = 2 * o;
    const int bb = 2 * o + 1;

    // ---- loop-invariant constants ----
    const int atom = ba / SHPA;
    const float cx = atom_coords[atom * 3 + 0];
    const float cy = atom_coords[atom * 3 + 1];
    const float cz = atom_coords[atom * 3 + 2];
    const u64 NCX = pk2(-cx, -cx), NCY = pk2(-cy, -cy), NCZ = pk2(-cz, -cz);

    const float na0 = -bas_exp[ba] * LOG2E;
    const float na1 = -bas_exp[bb] * LOG2E;
    const u64 NA0 = pk2(na0, na0), NA1 = pk2(na1, na1);

    const float c0 = norm_cst[ba] * bas_coeffs[ba];
    const float c1 = norm_cst[bb] * bas_coeffs[bb];

    const int n0 = (int)bas_n[ba], n1 = (int)bas_n[bb];
    const int kx0 = bas_kxyz[ba*3+0], ky0 = bas_kxyz[ba*3+1], kz0 = bas_kxyz[ba*3+2];
    const int kx1 = bas_kxyz[bb*3+0], ky1 = bas_kxyz[bb*3+1], kz1 = bas_kxyz[bb*3+2];

    // One-hot Horner coefficients: x^k == A*x^2 + B*x + C, k in {0,1,2}.
    // Overall constant c folds into the r-polynomial.
    #define ONEHOT2(k, one) ((k)==2 ? (one) : 0.0f)
    #define ONEHOT1(k, one) ((k)==1 ? (one) : 0.0f)
    #define ONEHOT0(k, one) ((k)==0 ? (one) : 0.0f)
    #define BPAIR(v) pk2((v), (v))

    const u64 AX0 = BPAIR(ONEHOT2(kx0,1.f)), BX0 = BPAIR(ONEHOT1(kx0,1.f)), CX0 = BPAIR(ONEHOT0(kx0,1.f));
    const u64 AY0 = BPAIR(ONEHOT2(ky0,1.f)), BY0 = BPAIR(ONEHOT1(ky0,1.f)), CY0 = BPAIR(ONEHOT0(ky0,1.f));
    const u64 AZ0 = BPAIR(ONEHOT2(kz0,1.f)), BZ0 = BPAIR(ONEHOT1(kz0,1.f)), CZ0 = BPAIR(ONEHOT0(kz0,1.f));
    const u64 AR0 = BPAIR(ONEHOT2(n0,c0)),   BR0 = BPAIR(ONEHOT1(n0,c0)),   CR0 = BPAIR(ONEHOT0(n0,c0));

    const u64 AX1 = BPAIR(ONEHOT2(kx1,1.f)), BX1 = BPAIR(ONEHOT1(kx1,1.f)), CX1 = BPAIR(ONEHOT0(kx1,1.f));
    const u64 AY1 = BPAIR(ONEHOT2(ky1,1.f)), BY1 = BPAIR(ONEHOT1(ky1,1.f)), CY1 = BPAIR(ONEHOT0(ky1,1.f));
    const u64 AZ1 = BPAIR(ONEHOT2(kz1,1.f)), BZ1 = BPAIR(ONEHOT1(kz1,1.f)), CZ1 = BPAIR(ONEHOT0(kz1,1.f));
    const u64 AR1 = BPAIR(ONEHOT2(n1,c1)),   BR1 = BPAIR(ONEHOT1(n1,c1)),   CR1 = BPAIR(ONEHOT0(n1,c1));

    float* op = out + ((size_t)b * NELEC + e0) * NORB + o;

    #pragma unroll 2
    for (int p = 0; p < NPAIRS; ++p) {
        // LDS.64 loads a ready-made f32x2 pair (electrons 2p, 2p+1).
        const u64 XP = *(const u64*)&s_pos[0][2 * p];
        const u64 YP = *(const u64*)&s_pos[1][2 * p];
        const u64 ZP = *(const u64*)&s_pos[2][2 * p];

        const u64 DX = add2(XP, NCX);
        const u64 DY = add2(YP, NCY);
        const u64 DZ = add2(ZP, NCZ);
        const u64 R2 = fma2(DZ, DZ, fma2(DY, DY, mul2(DX, DX)));

        float r2a, r2b;
        upk2(R2, r2a, r2b);
        const float rsa = rsqf(fmaxf(r2a, 1e-36f));
        const float rsb = rsqf(fmaxf(r2b, 1e-36f));
        const u64 R = mul2(R2, pk2(rsa, rsb));   // r = r2 * rsqrt(r2)

        // gaussians (EX2 is scalar MUFU)
        float e0a, e0b, e1a, e1b;
        upk2(mul2(NA0, R2), e0a, e0b);
        upk2(mul2(NA1, R2), e1a, e1b);
        const u64 G0 = pk2(ex2f(e0a), ex2f(e0b));
        const u64 G1 = pk2(ex2f(e1a), ex2f(e1b));

        // basis 0: (x^kx)(y^ky)(z^kz)(c*r^n)
        const u64 PX0 = fma2(fma2(AX0, DX, BX0), DX, CX0);
        const u64 PY0 = fma2(fma2(AY0, DY, BY0), DY, CY0);
        const u64 PZ0 = fma2(fma2(AZ0, DZ, BZ0), DZ, CZ0);
        const u64 PR0 = fma2(AR0, R2, fma2(BR0, R, CR0));
        const u64 M0  = mul2(mul2(PX0, PY0), mul2(PZ0, PR0));

        // basis 1
        const u64 PX1 = fma2(fma2(AX1, DX, BX1), DX, CX1);
        const u64 PY1 = fma2(fma2(AY1, DY, BY1), DY, CY1);
        const u64 PZ1 = fma2(fma2(AZ1, DZ, BZ1), DZ, CZ1);
        const u64 PR1 = fma2(AR1, R2, fma2(BR1, R, CR1));
        const u64 M1  = mul2(mul2(PX1, PY1), mul2(PZ1, PR1));

        const u64 V = fma2(M1, G1, mul2(M0, G0));   // lanes = the two electrons

        float va, vb;
        upk2(V, va, vb);
        op[(size_t)(2 * p) * NORB]     = va;
        op[(size_t)(2 * p + 1) * NORB] = vb;
    }
}

extern "C" void kernel_launch(void* const* d_in, const int* in_sizes, int n_in,
                              void* d_out, int out_size)
{
    const float* pos         = (const float*)d_in[0];
    const float* atom_coords = (const float*)d_in[1];
    const float* bas_exp     = (const float*)d_in[2];
    const float* bas_n       = (const float*)d_in[3];
    const float* norm_cst    = (const float*)d_in[4];
    const float* bas_coeffs  = (const float*)d_in[5];
    const int*   bas_kxyz    = (const int*)d_in[6];
    // d_in[7] = index_ctr: repeat(arange(NORB), NCTR) — encoded structurally.
    float* out = (float*)d_out;

    dim3 grid(NB, NCHUNK);
    ao_kernel<<<grid, NTHREADS>>>(pos, atom_coords, bas_exp, bas_n,
                                  norm_cst, bas_coeffs, bas_kxyz, out);
}

// round 7
// speedup vs baseline: 2.5584x; 1.0767x over previous
#include <cuda_runtime.h>

#define NB      512
#define NELEC   100
#define SHPA    30
#define NORB    300

#define ECHUNK  20               // electrons per CTA (even: processed in f32x2 pairs)
#define NCHUNK  5                // 100 / 20
#define NPAIRS  (ECHUNK / 2)
#define NTHREADS 320             // 300 active (one per orbital)

typedef unsigned long long u64;

// ---- f32x2 packed helpers (ptxas never auto-fuses; PTX-only path) ----
__device__ __forceinline__ u64 pk2(float lo, float hi) {
    u64 r; asm("mov.b64 %0,{%1,%2};" : "=l"(r) : "f"(lo), "f"(hi)); return r;
}
__device__ __forceinline__ void upk2(u64 v, float& lo, float& hi) {
    asm("mov.b64 {%0,%1}, %2;" : "=f"(lo), "=f"(hi) : "l"(v));
}
__device__ __forceinline__ u64 fma2(u64 a, u64 b, u64 c) {
    u64 d; asm("fma.rn.f32x2 %0,%1,%2,%3;" : "=l"(d) : "l"(a), "l"(b), "l"(c)); return d;
}
__device__ __forceinline__ u64 mul2(u64 a, u64 b) {
    u64 d; asm("mul.rn.f32x2 %0,%1,%2;" : "=l"(d) : "l"(a), "l"(b)); return d;
}
__device__ __forceinline__ u64 add2(u64 a, u64 b) {
    u64 d; asm("add.rn.f32x2 %0,%1,%2;" : "=l"(d) : "l"(a), "l"(b)); return d;
}
__device__ __forceinline__ float ex2f(float x) {
    float y; asm("ex2.approx.ftz.f32 %0, %1;" : "=f"(y) : "f"(x)); return y;
}
__device__ __forceinline__ float rsqf(float x) {
    float y; asm("rsqrt.approx.ftz.f32 %0, %1;" : "=f"(y) : "f"(x)); return y;
}

#define LOG2E 1.4426950408889634f

__global__ void __launch_bounds__(NTHREADS, 3)
ao_kernel(const float* __restrict__ pos,
          const float* __restrict__ atom_coords,
          const float* __restrict__ bas_exp,
          const float* __restrict__ bas_n,
          const float* __restrict__ norm_cst,
          const float* __restrict__ bas_coeffs,
          const int*   __restrict__ bas_kxyz,
          float* __restrict__ out)
{
    __shared__ __align__(16) float s_pos[3][ECHUNK];   // transposed: [comp][electron]

    const int b   = blockIdx.x;
    const int e0  = blockIdx.y * ECHUNK;
    const int tid = threadIdx.x;

    // Stage this chunk's electron positions, transposed for LDS.64 pair loads.
    if (tid < ECHUNK * 3) {
        const int e = tid / 3, c = tid % 3;
        s_pos[c][e] = pos[(size_t)b * (NELEC * 3) + (e0 + e) * 3 + c];
    }
    __syncthreads();

    if (tid >= NORB) return;
    const int o  = tid;
    const int ba = 2 * o;
    const int bb = 2 * o + 1;

    // ---- loop-invariant constants ----
    const int atom = ba / SHPA;
    const float cx = atom_coords[atom * 3 + 0];
    const float cy = atom_coords[atom * 3 + 1];
    const float cz = atom_coords[atom * 3 + 2];
    const u64 NCX = pk2(-cx, -cx), NCY = pk2(-cy, -cy), NCZ = pk2(-cz, -cz);

    const float na0 = -bas_exp[ba] * LOG2E;
    const float na1 = -bas_exp[bb] * LOG2E;
    const u64 NA0 = pk2(na0, na0), NA1 = pk2(na1, na1);

    const float c0 = norm_cst[ba] * bas_coeffs[ba];
    const float c1 = norm_cst[bb] * bas_coeffs[bb];
    const u64 CC0 = pk2(c0, c0), CC1 = pk2(c1, c1);

    const int n0 = (int)bas_n[ba], n1 = (int)bas_n[bb];
    const bool n0_1 = (n0 == 1), n0_2 = (n0 == 2);
    const bool n1_1 = (n1 == 1), n1_2 = (n1 == 2);

    const int kx0 = bas_kxyz[ba*3+0], ky0 = bas_kxyz[ba*3+1], kz0 = bas_kxyz[ba*3+2];
    const int kx1 = bas_kxyz[bb*3+0], ky1 = bas_kxyz[bb*3+1], kz1 = bas_kxyz[bb*3+2];

    // One-hot Horner coefficients for the cartesian factors: x^k == A*x^2 + B*x + C.
    #define ONEHOT2(k) ((k)==2 ? 1.0f : 0.0f)
    #define ONEHOT1(k) ((k)==1 ? 1.0f : 0.0f)
    #define ONEHOT0(k) ((k)==0 ? 1.0f : 0.0f)
    #define BPAIR(v) pk2((v), (v))

    const u64 AX0 = BPAIR(ONEHOT2(kx0)), BX0 = BPAIR(ONEHOT1(kx0)), CX0 = BPAIR(ONEHOT0(kx0));
    const u64 AY0 = BPAIR(ONEHOT2(ky0)), BY0 = BPAIR(ONEHOT1(ky0)), CY0 = BPAIR(ONEHOT0(ky0));
    const u64 AZ0 = BPAIR(ONEHOT2(kz0)), BZ0 = BPAIR(ONEHOT1(kz0)), CZ0 = BPAIR(ONEHOT0(kz0));
    const u64 AX1 = BPAIR(ONEHOT2(kx1)), BX1 = BPAIR(ONEHOT1(kx1)), CX1 = BPAIR(ONEHOT0(kx1));
    const u64 AY1 = BPAIR(ONEHOT2(ky1)), BY1 = BPAIR(ONEHOT1(ky1)), CY1 = BPAIR(ONEHOT0(ky1));
    const u64 AZ1 = BPAIR(ONEHOT2(kz1)), BZ1 = BPAIR(ONEHOT1(kz1)), CZ1 = BPAIR(ONEHOT0(kz1));

    const u64 ONEP = pk2(1.0f, 1.0f);

    float* op = out + ((size_t)b * NELEC + e0) * NORB + o;

    #pragma unroll 5
    for (int p = 0; p < NPAIRS; ++p) {
        // LDS.64 loads a ready-made f32x2 pair (electrons 2p, 2p+1).
        const u64 XP = *(const u64*)&s_pos[0][2 * p];
        const u64 YP = *(const u64*)&s_pos[1][2 * p];
        const u64 ZP = *(const u64*)&s_pos[2][2 * p];

        const u64 DX = add2(XP, NCX);
        const u64 DY = add2(YP, NCY);
        const u64 DZ = add2(ZP, NCZ);
        const u64 R2 = fma2(DZ, DZ, fma2(DY, DY, mul2(DX, DX)));

        float r2a, r2b;
        upk2(R2, r2a, r2b);
        const float rsa = rsqf(fmaxf(r2a, 1e-36f));
        const float rsb = rsqf(fmaxf(r2b, 1e-36f));
        const u64 R = mul2(R2, pk2(rsa, rsb));   // r = r2 * rsqrt(r2)

        // gaussians (EX2 is scalar MUFU)
        float e0a, e0b, e1a, e1b;
        upk2(mul2(NA0, R2), e0a, e0b);
        upk2(mul2(NA1, R2), e1a, e1b);
        const u64 G0 = pk2(ex2f(e0a), ex2f(e0b));
        const u64 G1 = pk2(ex2f(e1a), ex2f(e1b));

        // radial power via predicate select (no coefficient GPRs): c * r^n
        const u64 RSEL0 = n0_2 ? R2 : (n0_1 ? R : ONEP);
        const u64 RSEL1 = n1_2 ? R2 : (n1_1 ? R : ONEP);
        const u64 PR0 = mul2(CC0, RSEL0);
        const u64 PR1 = mul2(CC1, RSEL1);

        // cartesian harmonics via one-hot Horner (FMA pipe)
        const u64 PX0 = fma2(fma2(AX0, DX, BX0), DX, CX0);
        const u64 PY0 = fma2(fma2(AY0, DY, BY0), DY, CY0);
        const u64 PZ0 = fma2(fma2(AZ0, DZ, BZ0), DZ, CZ0);
        const u64 M0  = mul2(mul2(PX0, PY0), mul2(PZ0, PR0));

        const u64 PX1 = fma2(fma2(AX1, DX, BX1), DX, CX1);
        const u64 PY1 = fma2(fma2(AY1, DY, BY1), DY, CY1);
        const u64 PZ1 = fma2(fma2(AZ1, DZ, BZ1), DZ, CZ1);
        const u64 M1  = mul2(mul2(PX1, PY1), mul2(PZ1, PR1));

        const u64 V = fma2(M1, G1, mul2(M0, G0));   // lanes = the two electrons

        float va, vb;
        upk2(V, va, vb);
        op[(size_t)(2 * p) * NORB]     = va;
        op[(size_t)(2 * p + 1) * NORB] = vb;
    }
}

extern "C" void kernel_launch(void* const* d_in, const int* in_sizes, int n_in,
                              void* d_out, int out_size)
{
    const float* pos         = (const float*)d_in[0];
    const float* atom_coords = (const float*)d_in[1];
    const float* bas_exp     = (const float*)d_in[2];
    const float* bas_n       = (const float*)d_in[3];
    const float* norm_cst    = (const float*)d_in[4];
    const float* bas_coeffs  = (const float*)d_in[5];
    const int*   bas_kxyz    = (const int*)d_in[6];
    // d_in[7] = index_ctr: repeat(arange(NORB), NCTR) — encoded structurally.
    float* out = (float*)d_out;

    dim3 grid(NB, NCHUNK);
    ao_kernel<<<grid, NTHREADS>>>(pos, atom_coords, bas_exp, bas_n,
                                  norm_cst, bas_coeffs, bas_kxyz, out);
}